// round 14
// baseline (speedup 1.0000x reference)
#include <cuda_runtime.h>

#define D_IN   2048
#define T_TOT  1000
#define NB     20
#define N_NEUR 512
#define MAXROWS 512
#define NTH2   224          // 7 warps; 147 blocks cover 32768 pair-jobs

__device__ float g_rowmin[MAXROWS];
__device__ float g_rowmax[MAXROWS];

// ---------- kernel 1: per-row min/max ----------
__global__ void __launch_bounds__(512, 1)
rowstat_kernel(const float* __restrict__ x, int nrows)
{
    __shared__ float redmin[16], redmax[16];
    const int b   = blockIdx.x;
    const int tid = threadIdx.x;
    if (b >= nrows) return;
    const float* row = x + b * D_IN;

    float v0 = row[tid], v1 = row[tid + 512], v2 = row[tid + 1024], v3 = row[tid + 1536];
    float pmin = fminf(fminf(v0, v1), fminf(v2, v3));
    float pmax = fmaxf(fmaxf(v0, v1), fmaxf(v2, v3));
    #pragma unroll
    for (int o = 16; o; o >>= 1) {
        pmin = fminf(pmin, __shfl_xor_sync(0xffffffffu, pmin, o));
        pmax = fmaxf(pmax, __shfl_xor_sync(0xffffffffu, pmax, o));
    }
    const int wid = tid >> 5, lid = tid & 31;
    if (lid == 0) { redmin[wid] = pmin; redmax[wid] = pmax; }
    __syncthreads();
    if (wid == 0) {
        float a  = redmin[lid & 15];
        float mx = redmax[lid & 15];
        #pragma unroll
        for (int o = 8; o; o >>= 1) {
            a  = fminf(a,  __shfl_xor_sync(0xffffffffu, a,  o));
            mx = fmaxf(mx, __shfl_xor_sync(0xffffffffu, mx, o));
        }
        if (lid == 0) { g_rowmin[b] = a; g_rowmax[b] = mx; }
    }
}

// IC: reciprocal-multiply normalize (verified fast-math lowering), clip
__device__ __forceinline__ float make_ic(const float* __restrict__ x, int row, int nidx)
{
    const float xmin = g_rowmin[row];
    const float xmax = g_rowmax[row];
    const float xi   = x[row * D_IN + nidx];
    const float den  = __fadd_rn(__fsub_rn(xmax, xmin), 1e-10f);
    const float rden = __fdiv_rn(1.0f, den);
    const float xn   = __fmul_rn(__fsub_rn(xi, xmin), rden);
    return fminf(fmaxf(xn, 0.01f), 0.99f);
}

// features from per-chain accumulators + thread-private smem hist column
__device__ __forceinline__ float4 make_feats(int cnt, int first, int last, float acc,
                                             const int* __restrict__ histcol)
{
    const float mfr = __fdiv_rn((float)cnt, 1000.0f);
    const float mft = (cnt > 1)
        ? __fdiv_rn((float)(last - first), (float)(cnt - 1))
        : 1000.0f;
    const float me = __fdiv_rn(acc, 1000.0f);

    float h[NB], hsum = 0.0f;
    #pragma unroll
    for (int j = 0; j < NB; j++) {
        h[j] = __fdiv_rn((float)histcol[j * NTH2], 50.0f);
        hsum = __fadd_rn(hsum, h[j]);
    }
    const float pden = __fadd_rn(hsum, 1e-10f);
    float q[NB], qsum = 0.0f;
    #pragma unroll
    for (int j = 0; j < NB; j++) {
        float p = __fdiv_rn(h[j], pden);
        q[j] = __fadd_rn(p, 1e-10f);
        qsum = __fadd_rn(qsum, q[j]);
    }
    float ment = 0.0f;
    #pragma unroll
    for (int j = 0; j < NB; j++) {
        float qq = __fdiv_rn(q[j], qsum);
        ment = __fadd_rn(ment, __fmul_rn(qq, logf(qq)));
    }
    float4 o;
    o.x = mft; o.y = mfr; o.z = me; o.w = -ment;
    return o;
}

// ---------- kernel 2: two independent chains per thread (ILP-2) ----------
__global__ void __launch_bounds__(NTH2, 1)
chaosfex_kernel(const float* __restrict__ x, float* __restrict__ out, int jobs)
{
    __shared__ int hist[2 * NB * NTH2];      // 35840 B: chain A cols [0,20), B cols [20,40)
    const int tid = threadIdx.x;
    const int g   = blockIdx.x * NTH2 + tid;
    if (g >= jobs) return;

    const int gB  = g + jobs;                // second chain
    const int n   = g & (N_NEUR - 1);        // same neuron index for both chains
    const int rowA = g  >> 9;
    const int rowB = gB >> 9;

    int* hA = hist + tid;                    // stride NTH2 columns
    int* hB = hist + NB * NTH2 + tid;
    #pragma unroll
    for (int j = 0; j < NB; j++) { hA[j * NTH2] = 0; hB[j * NTH2] = 0; }

    const int nidx = (n == 511) ? 2047 : (int)((double)n * (2047.0 / 511.0));

    float sA = make_ic(x, rowA, nidx);
    float sB = make_ic(x, rowB, nidx);

    float accA = __fmul_rn(sA, sA), accB = __fmul_rn(sB, sB);
    int cntA = 0, firstA = 1 << 30, lastA = -1;
    int cntB = 0, firstB = 1 << 30, lastB = -1;
    bool prevA = sA > 0.5f, prevB = sB > 0.5f;

    hA[((int)__fmul_rn(sA, 20.0f)) * NTH2] += 1;
    hB[((int)__fmul_rn(sB, 20.0f)) * NTH2] += 1;

    // Map B: m = rn(0.1*s); sum = fma(m,s,s); conditional wrap (exact).
    #pragma unroll 3
    for (int t = 1; t < T_TOT; t++) {
        float mA = __fmul_rn(0.1f, sA);
        float mB = __fmul_rn(0.1f, sB);
        float uA = __fmaf_rn(mA, sA, sA);
        float uB = __fmaf_rn(mB, sB, sB);
        sA = (uA >= 1.0f) ? __fadd_rn(uA, -1.0f) : uA;
        sB = (uB >= 1.0f) ? __fadd_rn(uB, -1.0f) : uB;

        bool aA = sA > 0.5f, aB = sB > 0.5f;
        bool cA = aA && !prevA, cB = aB && !prevB;
        prevA = aA; prevB = aB;
        if (cA) { cntA++; lastA = t; firstA = min(firstA, t); }
        if (cB) { cntB++; lastB = t; firstB = min(firstB, t); }

        accA = __fmaf_rn(sA, sA, accA);
        accB = __fmaf_rn(sB, sB, accB);

        hA[((int)__fmul_rn(sA, 20.0f)) * NTH2] += 1;   // s in [0,1): bin in [0,19]
        hB[((int)__fmul_rn(sB, 20.0f)) * NTH2] += 1;
    }

    float4 oA = make_feats(cntA, firstA, lastA, accA, hA);
    float4 oB = make_feats(cntB, firstB, lastB, accB, hB);
    reinterpret_cast<float4*>(out)[g]  = oA;
    reinterpret_cast<float4*>(out)[gB] = oB;
}

extern "C" void kernel_launch(void* const* d_in, const int* in_sizes, int n_in,
                              void* d_out, int out_size)
{
    const float* x = (const float*)d_in[0];
    float* out = (float*)d_out;
    const int B = in_sizes[0] / D_IN;          // 128
    const int total = B * N_NEUR;              // 65536
    const int jobs  = total / 2;               // 32768 (total is even: B*512)
    const int grid  = (jobs + NTH2 - 1) / NTH2;   // 147

    rowstat_kernel<<<B, 512>>>(x, B);
    chaosfex_kernel<<<grid, NTH2>>>(x, out, jobs);
}

// round 15
// speedup vs baseline: 1.3552x; 1.3552x over previous
#include <cuda_runtime.h>

#define D_IN   2048
#define T_TOT  1000
#define NB     20
#define N_NEUR 512
#define MAXROWS 512
#define NTH    448

__device__ float g_rowmin[MAXROWS];
__device__ float g_rowmax[MAXROWS];

// ---------- kernel 1: per-row min/max ----------
__global__ void __launch_bounds__(512, 1)
rowstat_kernel(const float* __restrict__ x, int nrows)
{
    __shared__ float redmin[16], redmax[16];
    const int b   = blockIdx.x;
    const int tid = threadIdx.x;
    if (b >= nrows) return;
    const float* row = x + b * D_IN;

    float v0 = row[tid], v1 = row[tid + 512], v2 = row[tid + 1024], v3 = row[tid + 1536];
    float pmin = fminf(fminf(v0, v1), fminf(v2, v3));
    float pmax = fmaxf(fmaxf(v0, v1), fmaxf(v2, v3));
    #pragma unroll
    for (int o = 16; o; o >>= 1) {
        pmin = fminf(pmin, __shfl_xor_sync(0xffffffffu, pmin, o));
        pmax = fmaxf(pmax, __shfl_xor_sync(0xffffffffu, pmax, o));
    }
    const int wid = tid >> 5, lid = tid & 31;
    if (lid == 0) { redmin[wid] = pmin; redmax[wid] = pmax; }
    __syncthreads();
    if (wid == 0) {
        float a  = redmin[lid & 15];
        float mx = redmax[lid & 15];
        #pragma unroll
        for (int o = 8; o; o >>= 1) {
            a  = fminf(a,  __shfl_xor_sync(0xffffffffu, a,  o));
            mx = fmaxf(mx, __shfl_xor_sync(0xffffffffu, mx, o));
        }
        if (lid == 0) { g_rowmin[b] = a; g_rowmax[b] = mx; }
    }
}

// one map step: variant B (fma contraction) + exact conditional wrap
__device__ __forceinline__ float gls_step(float s)
{
    float m   = __fmul_rn(0.1f, s);
    float u   = __fmaf_rn(m, s, s);
    float um1 = __fadd_rn(u, -1.0f);
    return (u >= 1.0f) ? um1 : u;     // FSETP + FSEL (pred-as-data)
}

// ---------- kernel 2: trajectories + features ----------
__global__ void __launch_bounds__(NTH, 1)
chaosfex_kernel(const float* __restrict__ x, float* __restrict__ out, int total)
{
    // parity-split thread-private histograms:
    //   histE = hist[bin*NTH + tid], histO = hist[NB*NTH + bin*NTH + tid]
    // consecutive-iteration same-bin RMWs land on different addresses -> no
    // LDS-after-STS same-address stall (sm_100 smem has no store-forward).
    extern __shared__ int hist[];              // 2 * NB * NTH ints = 70 KB
    const int tid = threadIdx.x;
    const int g   = blockIdx.x * NTH + tid;
    if (g >= total) return;

    int* hE = hist + tid;
    int* hO = hist + NB * NTH + tid;
    #pragma unroll
    for (int j = 0; j < NB; j++) { hE[j * NTH] = 0; hO[j * NTH] = 0; }

    const int row = g >> 9;
    const int n   = g & (N_NEUR - 1);

    // ---- IC: reciprocal-multiply normalize (verified lowering), clip ----
    const int   nidx = (n == 511) ? 2047 : (int)((double)n * (2047.0 / 511.0));
    const float xmin = g_rowmin[row];
    const float xmax = g_rowmax[row];
    const float xi   = x[row * D_IN + nidx];
    const float den  = __fadd_rn(__fsub_rn(xmax, xmin), 1e-10f);
    const float rden = __fdiv_rn(1.0f, den);
    const float xn   = __fmul_rn(__fsub_rn(xi, xmin), rden);
    float s = fminf(fmaxf(xn, 0.01f), 0.99f);

    float acc   = __fmul_rn(s, s);
    int   cnt   = 0;
    int   first = 1 << 30;
    int   last  = -1;
    bool  prev  = s > 0.5f;

    hE[((int)__fmul_rn(s, 20.0f)) * NTH] += 1;     // step 0 -> even buffer

    // 999 steps: 499 pairs (odd->hO, even->hE) + final odd step
    #pragma unroll 4
    for (int t = 1; t < T_TOT - 1; t += 2) {
        // odd step t
        s = gls_step(s);
        {
            bool a = s > 0.5f;
            bool c = a && !prev;
            prev = a;
            if (c) { cnt++; last = t; first = min(first, t); }
            acc = __fmaf_rn(s, s, acc);
            hO[((int)__fmul_rn(s, 20.0f)) * NTH] += 1;
        }
        // even step t+1
        s = gls_step(s);
        {
            bool a = s > 0.5f;
            bool c = a && !prev;
            prev = a;
            if (c) { cnt++; last = t + 1; first = min(first, t + 1); }
            acc = __fmaf_rn(s, s, acc);
            hE[((int)__fmul_rn(s, 20.0f)) * NTH] += 1;
        }
    }
    // final step t = 999 (odd)
    {
        s = gls_step(s);
        bool a = s > 0.5f;
        bool c = a && !prev;
        if (c) { cnt++; last = T_TOT - 1; first = min(first, T_TOT - 1); }
        acc = __fmaf_rn(s, s, acc);
        hO[((int)__fmul_rn(s, 20.0f)) * NTH] += 1;
    }

    // ---- scalar features (uniform +1 time shift cancels in last-first) ----
    const float mfr = __fdiv_rn((float)cnt, 1000.0f);
    const float mft = (cnt > 1)
        ? __fdiv_rn((float)(last - first), (float)(cnt - 1))
        : 1000.0f;
    const float me = __fdiv_rn(acc, 1000.0f);

    // ---- entropy (counts = E + O) ----
    float h[NB], hsum = 0.0f;
    #pragma unroll
    for (int j = 0; j < NB; j++) {
        int c = hE[j * NTH] + hO[j * NTH];
        h[j] = __fdiv_rn((float)c, 50.0f);
        hsum = __fadd_rn(hsum, h[j]);
    }
    const float pden = __fadd_rn(hsum, 1e-10f);
    float q[NB], qsum = 0.0f;
    #pragma unroll
    for (int j = 0; j < NB; j++) {
        float p = __fdiv_rn(h[j], pden);
        q[j] = __fadd_rn(p, 1e-10f);
        qsum = __fadd_rn(qsum, q[j]);
    }
    float ment = 0.0f;
    #pragma unroll
    for (int j = 0; j < NB; j++) {
        float qq = __fdiv_rn(q[j], qsum);
        ment = __fadd_rn(ment, __fmul_rn(qq, logf(qq)));
    }

    float4 o;
    o.x = mft; o.y = mfr; o.z = me; o.w = -ment;
    reinterpret_cast<float4*>(out)[g] = o;
}

extern "C" void kernel_launch(void* const* d_in, const int* in_sizes, int n_in,
                              void* d_out, int out_size)
{
    const float* x = (const float*)d_in[0];
    float* out = (float*)d_out;
    const int B = in_sizes[0] / D_IN;          // 128
    const int total = B * N_NEUR;              // 65536
    const int grid  = (total + NTH - 1) / NTH; // 147
    const int smem  = 2 * NB * NTH * (int)sizeof(int);   // 71680 B

    cudaFuncSetAttribute(chaosfex_kernel,
                         cudaFuncAttributeMaxDynamicSharedMemorySize, smem);

    rowstat_kernel<<<B, 512>>>(x, B);
    chaosfex_kernel<<<grid, NTH, smem>>>(x, out, total);
}

// round 16
// speedup vs baseline: 1.5179x; 1.1201x over previous
#include <cuda_runtime.h>

#define D_IN   2048
#define T_TOT  1000
#define NB     20
#define N_NEUR 512
#define MAXROWS 512
#define NTH    448

__device__ float g_rowmin[MAXROWS];
__device__ float g_rowmax[MAXROWS];

// ---------- kernel 1: per-row min/max ----------
__global__ void __launch_bounds__(512, 1)
rowstat_kernel(const float* __restrict__ x, int nrows)
{
    __shared__ float redmin[16], redmax[16];
    const int b   = blockIdx.x;
    const int tid = threadIdx.x;
    if (b >= nrows) return;
    const float* row = x + b * D_IN;

    float v0 = row[tid], v1 = row[tid + 512], v2 = row[tid + 1024], v3 = row[tid + 1536];
    float pmin = fminf(fminf(v0, v1), fminf(v2, v3));
    float pmax = fmaxf(fmaxf(v0, v1), fmaxf(v2, v3));
    #pragma unroll
    for (int o = 16; o; o >>= 1) {
        pmin = fminf(pmin, __shfl_xor_sync(0xffffffffu, pmin, o));
        pmax = fmaxf(pmax, __shfl_xor_sync(0xffffffffu, pmax, o));
    }
    const int wid = tid >> 5, lid = tid & 31;
    if (lid == 0) { redmin[wid] = pmin; redmax[wid] = pmax; }
    __syncthreads();
    if (wid == 0) {
        float a  = redmin[lid & 15];
        float mx = redmax[lid & 15];
        #pragma unroll
        for (int o = 8; o; o >>= 1) {
            a  = fminf(a,  __shfl_xor_sync(0xffffffffu, a,  o));
            mx = fmaxf(mx, __shfl_xor_sync(0xffffffffu, mx, o));
        }
        if (lid == 0) { g_rowmin[b] = a; g_rowmax[b] = mx; }
    }
}

// one map step: variant B (fma contraction) + exact conditional wrap
__device__ __forceinline__ float gls_step(float s)
{
    float m   = __fmul_rn(0.1f, s);
    float u   = __fmaf_rn(m, s, s);
    float um1 = __fadd_rn(u, -1.0f);
    return (u >= 1.0f) ? um1 : u;
}

// ---------- kernel 2: trajectories + features ----------
__global__ void __launch_bounds__(NTH, 1)
chaosfex_kernel(const float* __restrict__ x, float* __restrict__ out, int total)
{
    // thread-private histogram columns; updates via no-return shared atomics
    // (ATOMS.ADD): 1 issue slot, no load-latency chain, lane-spread addresses.
    __shared__ int hist[NB * NTH];             // 35840 B
    const int tid = threadIdx.x;
    const int g   = blockIdx.x * NTH + tid;
    if (g >= total) return;

    int* hc = hist + tid;                      // column base, stride NTH
    #pragma unroll
    for (int j = 0; j < NB; j++) hc[j * NTH] = 0;

    const int row = g >> 9;
    const int n   = g & (N_NEUR - 1);

    // ---- IC: reciprocal-multiply normalize (verified lowering), clip ----
    const int   nidx = (n == 511) ? 2047 : (int)((double)n * (2047.0 / 511.0));
    const float xmin = g_rowmin[row];
    const float xmax = g_rowmax[row];
    const float xi   = x[row * D_IN + nidx];
    const float den  = __fadd_rn(__fsub_rn(xmax, xmin), 1e-10f);
    const float rden = __fdiv_rn(1.0f, den);
    const float xn   = __fmul_rn(__fsub_rn(xi, xmin), rden);
    float s = fminf(fmaxf(xn, 0.01f), 0.99f);

    float acc   = __fmul_rn(s, s);
    int   cnt   = 0;
    int   first = 1 << 30;
    int   last  = -1;
    bool  prev  = s > 0.5f;

    atomicAdd(&hc[((int)__fmul_rn(s, 20.0f)) * NTH], 1);   // step 0

    #pragma unroll 4
    for (int t = 1; t < T_TOT; t++) {
        s = gls_step(s);

        bool a = s > 0.5f;
        bool c = a && !prev;
        prev = a;
        if (c) { cnt++; last = t; first = min(first, t); }

        acc = __fmaf_rn(s, s, acc);

        // s in [0,1) always -> bin in [0,19], no clamp
        atomicAdd(&hc[((int)__fmul_rn(s, 20.0f)) * NTH], 1);
    }

    __syncthreads();   // drain pending shared atomics before plain LDS reads

    // ---- scalar features (uniform time shift cancels in last-first) ----
    const float mfr = __fdiv_rn((float)cnt, 1000.0f);
    const float mft = (cnt > 1)
        ? __fdiv_rn((float)(last - first), (float)(cnt - 1))
        : 1000.0f;
    const float me = __fdiv_rn(acc, 1000.0f);

    // ---- entropy ----
    float h[NB], hsum = 0.0f;
    #pragma unroll
    for (int j = 0; j < NB; j++) {
        h[j] = __fdiv_rn((float)hc[j * NTH], 50.0f);
        hsum = __fadd_rn(hsum, h[j]);
    }
    const float pden = __fadd_rn(hsum, 1e-10f);
    float q[NB], qsum = 0.0f;
    #pragma unroll
    for (int j = 0; j < NB; j++) {
        float p = __fdiv_rn(h[j], pden);
        q[j] = __fadd_rn(p, 1e-10f);
        qsum = __fadd_rn(qsum, q[j]);
    }
    float ment = 0.0f;
    #pragma unroll
    for (int j = 0; j < NB; j++) {
        float qq = __fdiv_rn(q[j], qsum);
        ment = __fadd_rn(ment, __fmul_rn(qq, logf(qq)));
    }

    float4 o;
    o.x = mft; o.y = mfr; o.z = me; o.w = -ment;
    reinterpret_cast<float4*>(out)[g] = o;
}

extern "C" void kernel_launch(void* const* d_in, const int* in_sizes, int n_in,
                              void* d_out, int out_size)
{
    const float* x = (const float*)d_in[0];
    float* out = (float*)d_out;
    const int B = in_sizes[0] / D_IN;          // 128
    const int total = B * N_NEUR;              // 65536
    const int grid  = (total + NTH - 1) / NTH; // 147

    rowstat_kernel<<<B, 512>>>(x, B);
    chaosfex_kernel<<<grid, NTH>>>(x, out, total);
}

// round 17
// speedup vs baseline: 1.5439x; 1.0171x over previous
#include <cuda_runtime.h>

#define D_IN   2048
#define T_TOT  1000
#define NB     20
#define N_NEUR 512
#define MAXROWS 512
#define NTH    448

__device__ float g_rowmin[MAXROWS];
__device__ float g_rowmax[MAXROWS];

// ---------- kernel 1: per-row min/max ----------
__global__ void __launch_bounds__(512, 1)
rowstat_kernel(const float* __restrict__ x, int nrows)
{
    __shared__ float redmin[16], redmax[16];
    const int b   = blockIdx.x;
    const int tid = threadIdx.x;
    if (b >= nrows) return;
    const float* row = x + b * D_IN;

    float v0 = row[tid], v1 = row[tid + 512], v2 = row[tid + 1024], v3 = row[tid + 1536];
    float pmin = fminf(fminf(v0, v1), fminf(v2, v3));
    float pmax = fmaxf(fmaxf(v0, v1), fmaxf(v2, v3));
    #pragma unroll
    for (int o = 16; o; o >>= 1) {
        pmin = fminf(pmin, __shfl_xor_sync(0xffffffffu, pmin, o));
        pmax = fmaxf(pmax, __shfl_xor_sync(0xffffffffu, pmax, o));
    }
    const int wid = tid >> 5, lid = tid & 31;
    if (lid == 0) { redmin[wid] = pmin; redmax[wid] = pmax; }
    __syncthreads();
    if (wid == 0) {
        float a  = redmin[lid & 15];
        float mx = redmax[lid & 15];
        #pragma unroll
        for (int o = 8; o; o >>= 1) {
            a  = fminf(a,  __shfl_xor_sync(0xffffffffu, a,  o));
            mx = fmaxf(mx, __shfl_xor_sync(0xffffffffu, mx, o));
        }
        if (lid == 0) { g_rowmin[b] = a; g_rowmax[b] = mx; }
    }
}

// one map step: variant B (fma contraction) + exact conditional wrap
__device__ __forceinline__ float gls_step(float s)
{
    float m   = __fmul_rn(0.1f, s);
    float u   = __fmaf_rn(m, s, s);
    float um1 = __fadd_rn(u, -1.0f);
    return (u >= 1.0f) ? um1 : u;
}

// ---------- kernel 2: trajectories + features ----------
__global__ void __launch_bounds__(NTH, 1)
chaosfex_kernel(const float* __restrict__ x, float* __restrict__ out, int total)
{
    // thread-private histogram columns; updates via no-return shared atomics
    // (ATOMS.ADD): 1 issue slot, no load-latency chain, lane-spread addresses.
    __shared__ int hist[NB * NTH];             // 35840 B
    const int tid = threadIdx.x;
    const int g   = blockIdx.x * NTH + tid;
    if (g >= total) return;

    int* hc = hist + tid;                      // column base, stride NTH
    #pragma unroll
    for (int j = 0; j < NB; j++) hc[j * NTH] = 0;

    const int row = g >> 9;
    const int n   = g & (N_NEUR - 1);

    // ---- IC: reciprocal-multiply normalize (verified lowering), clip ----
    const int   nidx = (n == 511) ? 2047 : (int)((double)n * (2047.0 / 511.0));
    const float xmin = g_rowmin[row];
    const float xmax = g_rowmax[row];
    const float xi   = x[row * D_IN + nidx];
    const float den  = __fadd_rn(__fsub_rn(xmax, xmin), 1e-10f);
    const float rden = __fdiv_rn(1.0f, den);
    const float xn   = __fmul_rn(__fsub_rn(xi, xmin), rden);
    float s = fminf(fmaxf(xn, 0.01f), 0.99f);

    float acc   = __fmul_rn(s, s);
    int   cnt   = 0;
    int   first = 1 << 30;
    int   last  = -1;
    bool  prev  = s > 0.5f;

    atomicAdd(&hc[((int)__fmul_rn(s, 20.0f)) * NTH], 1);   // step 0

    #pragma unroll 4
    for (int t = 1; t < T_TOT; t++) {
        s = gls_step(s);

        bool a = s > 0.5f;
        bool c = a && !prev;
        prev = a;
        if (c) { cnt++; last = t; first = min(first, t); }

        acc = __fmaf_rn(s, s, acc);

        // s in [0,1) always -> bin in [0,19], no clamp
        atomicAdd(&hc[((int)__fmul_rn(s, 20.0f)) * NTH], 1);
    }

    __syncthreads();   // drain pending shared atomics before plain LDS reads

    // ---- scalar features (uniform time shift cancels in last-first) ----
    const float mfr = __fdiv_rn((float)cnt, 1000.0f);
    const float mft = (cnt > 1)
        ? __fdiv_rn((float)(last - first), (float)(cnt - 1))
        : 1000.0f;
    const float me = __fdiv_rn(acc, 1000.0f);

    // ---- entropy ----
    float h[NB], hsum = 0.0f;
    #pragma unroll
    for (int j = 0; j < NB; j++) {
        h[j] = __fdiv_rn((float)hc[j * NTH], 50.0f);
        hsum = __fadd_rn(hsum, h[j]);
    }
    const float pden = __fadd_rn(hsum, 1e-10f);
    float q[NB], qsum = 0.0f;
    #pragma unroll
    for (int j = 0; j < NB; j++) {
        float p = __fdiv_rn(h[j], pden);
        q[j] = __fadd_rn(p, 1e-10f);
        qsum = __fadd_rn(qsum, q[j]);
    }
    float ment = 0.0f;
    #pragma unroll
    for (int j = 0; j < NB; j++) {
        float qq = __fdiv_rn(q[j], qsum);
        ment = __fadd_rn(ment, __fmul_rn(qq, logf(qq)));
    }

    float4 o;
    o.x = mft; o.y = mfr; o.z = me; o.w = -ment;
    reinterpret_cast<float4*>(out)[g] = o;
}

extern "C" void kernel_launch(void* const* d_in, const int* in_sizes, int n_in,
                              void* d_out, int out_size)
{
    const float* x = (const float*)d_in[0];
    float* out = (float*)d_out;
    const int B = in_sizes[0] / D_IN;          // 128
    const int total = B * N_NEUR;              // 65536
    const int grid  = (total + NTH - 1) / NTH; // 147

    rowstat_kernel<<<B, 512>>>(x, B);
    chaosfex_kernel<<<grid, NTH>>>(x, out, total);
}